// round 1
// baseline (speedup 1.0000x reference)
#include <cuda_runtime.h>

// Problem constants
#define BB   4
#define HH   128
#define WW   128
#define CC   256
#define GG   16
#define K2   9
#define CR   64
#define EE   144          // K2*G
#define BN_EPS 1e-3f

#define OUT1 (BB*HH*WW*CC)   // 16,777,216
#define OUT2 (BB*HH*WW*EE)   //  9,437,184

// Dynamic smem layout (floats):
//   hbuf   [0,      8320)   128*65 (padded)
//   kerbuf [8320,  26752)   128*144      (aliased by xs+w1s during phase 1)
//     xs   [8320,  16640)   128*65 (padded)
//     w1s  [16640, 20736)   64*64
//   w2s    [26752, 35968)   64*144
#define SMEM_FLOATS 35968
#define SMEM_BYTES  (SMEM_FLOATS * 4)

__global__ void __launch_bounds__(256)
invo_fused_kernel(const float* __restrict__ x,
                  const float* __restrict__ w1,
                  const float* __restrict__ b1,
                  const float* __restrict__ gamma,
                  const float* __restrict__ beta,
                  const float* __restrict__ bn_mean,
                  const float* __restrict__ bn_var,
                  const float* __restrict__ w2,
                  const float* __restrict__ b2,
                  float* __restrict__ out,
                  float* __restrict__ ker_out)
{
    extern __shared__ float smem[];
    float* hbuf   = smem;            // 128 x 65 (d fastest, padded)
    float* kerbuf = smem + 8320;     // 128 x 144
    float* xs     = smem + 8320;     // alias kerbuf (phase 1 only), 128 x 65
    float* w1s    = smem + 16640;    // 64 x 64
    float* w2s    = smem + 26752;    // 64 x 144

    const int t   = threadIdx.x;     // 0..255
    const int bid = blockIdx.x;      // 0..511
    const int b   = bid >> 7;
    const int h   = bid & 127;
    const int rowbase = ((b * HH + h) * WW) * CC;   // fits in int

    // ---------------- Phase 1: h = ReLU(BN(x @ w1 + b1)) ----------------
    // Thread tile: 4 pixels x 8 channels.
    const int pg    = t >> 3;        // 0..31
    const int dg    = t & 7;         // 0..7
    const int pbase = pg * 4;        // pixel base
    const int d0    = dg * 8;        // channel base

    float acc[4][8];
#pragma unroll
    for (int p = 0; p < 4; ++p)
#pragma unroll
        for (int i = 0; i < 8; ++i) acc[p][i] = 0.f;

    for (int kc = 0; kc < CC; kc += 64) {
        // stage x chunk: 128 px x 64 ch (padded rows of 65)
        for (int idx = t; idx < 128 * 64; idx += 256) {
            int wl = idx >> 6, j = idx & 63;
            xs[wl * 65 + j] = x[rowbase + wl * CC + kc + j];
        }
        // stage w1 chunk: 64 x 64
        for (int idx = t; idx < 64 * 64; idx += 256) {
            w1s[idx] = w1[(kc + (idx >> 6)) * CR + (idx & 63)];
        }
        __syncthreads();

#pragma unroll 8
        for (int j = 0; j < 64; ++j) {
            const float xv0 = xs[(pbase + 0) * 65 + j];
            const float xv1 = xs[(pbase + 1) * 65 + j];
            const float xv2 = xs[(pbase + 2) * 65 + j];
            const float xv3 = xs[(pbase + 3) * 65 + j];
#pragma unroll
            for (int i = 0; i < 8; ++i) {
                const float wv = w1s[j * 64 + d0 + i];
                acc[0][i] += xv0 * wv;
                acc[1][i] += xv1 * wv;
                acc[2][i] += xv2 * wv;
                acc[3][i] += xv3 * wv;
            }
        }
        __syncthreads();
    }

    // BN (inference) + ReLU, write hbuf
#pragma unroll
    for (int i = 0; i < 8; ++i) {
        const int d = d0 + i;
        const float s  = gamma[d] * rsqrtf(bn_var[d] + BN_EPS);
        const float sh = beta[d] + (b1[d] - bn_mean[d]) * s;
#pragma unroll
        for (int p = 0; p < 4; ++p) {
            const float v = acc[p][i] * s + sh;
            hbuf[(pbase + p) * 65 + d] = fmaxf(v, 0.f);
        }
    }

    // stage w2 (64 x 144)
    for (int idx = t; idx < 64 * 144; idx += 256)
        w2s[idx] = w2[idx];
    __syncthreads();   // hbuf + w2s visible; xs dead -> kerbuf may be written

    // ---------------- Phase 2: ker = h @ w2 + b2 ----------------
    // Thread tile: 2 pixels x 18 e-values, two passes over pixel pairs.
    const int eg  = t & 7;
    const int e0  = eg * 18;
    const int pg2 = t >> 3;          // 0..31

#pragma unroll 1
    for (int rep = 0; rep < 2; ++rep) {
        const int pb = (pg2 + 32 * rep) * 2;   // 0,2,...,126
        float a0[18], a1[18];
#pragma unroll
        for (int i = 0; i < 18; ++i) { a0[i] = 0.f; a1[i] = 0.f; }

#pragma unroll 4
        for (int j = 0; j < 64; ++j) {
            const float h0 = hbuf[pb * 65 + j];
            const float h1 = hbuf[pb * 65 + 65 + j];
#pragma unroll
            for (int i = 0; i < 18; ++i) {
                const float wv = w2s[j * 144 + e0 + i];
                a0[i] += h0 * wv;
                a1[i] += h1 * wv;
            }
        }

        const int gbase = ((b * HH + h) * WW + pb) * EE;
#pragma unroll
        for (int i = 0; i < 18; ++i) {
            const int e = e0 + i;
            const float bb = b2[e];
            const float v0 = a0[i] + bb;
            const float v1 = a1[i] + bb;
            kerbuf[pb * 144 + e]       = v0;
            kerbuf[(pb + 1) * 144 + e] = v1;
            if (ker_out) {
                ker_out[gbase + e]      = v0;
                ker_out[gbase + EE + e] = v1;
            }
        }
    }
    __syncthreads();

    // ---------------- Phase 3: involution ----------------
    // thread = channel c; loop over 128 pixels of this row.
    const int c = t;                 // 0..255
    const int g = c & 15;            // reshape (C) -> (C/G, G): g = c % G
    const float* xc = x + (b * HH * WW) * CC + c;
    float* oc = out + ((b * HH + h) * WW) * CC + c;

#pragma unroll 2
    for (int w = 0; w < WW; ++w) {
        const float* kw = &kerbuf[w * 144 + g];
        float a = 0.f;
#pragma unroll
        for (int ki = 0; ki < 3; ++ki) {
            const int hh = h + ki - 1;
            if (hh < 0 || hh >= HH) continue;
            const float* xr = xc + (hh * WW) * CC;
#pragma unroll
            for (int kj = 0; kj < 3; ++kj) {
                const int ww = w + kj - 1;
                if (ww < 0 || ww >= WW) continue;
                a += xr[ww * CC] * kw[(ki * 3 + kj) * 16];
            }
        }
        oc[w * CC] = a;
    }
}

extern "C" void kernel_launch(void* const* d_in, const int* in_sizes, int n_in,
                              void* d_out, int out_size) {
    const float* x       = (const float*)d_in[0];
    const float* w1      = (const float*)d_in[1];
    const float* b1      = (const float*)d_in[2];
    const float* gamma   = (const float*)d_in[3];
    const float* beta    = (const float*)d_in[4];
    const float* bn_mean = (const float*)d_in[5];
    const float* bn_var  = (const float*)d_in[6];
    const float* w2      = (const float*)d_in[7];
    const float* b2      = (const float*)d_in[8];

    float* out = (float*)d_out;
    // Reference returns (out, kernel): write kernel after out if space exists.
    float* ker_out = (out_size >= OUT1 + OUT2) ? out + OUT1 : (float*)0;

    cudaFuncSetAttribute(invo_fused_kernel,
                         cudaFuncAttributeMaxDynamicSharedMemorySize, SMEM_BYTES);

    invo_fused_kernel<<<BB * HH, 256, SMEM_BYTES>>>(
        x, w1, b1, gamma, beta, bn_mean, bn_var, w2, b2, out, ker_out);
}

// round 2
// speedup vs baseline: 3.0039x; 3.0039x over previous
#include <cuda_runtime.h>

// Problem constants
#define BB   4
#define HH   128
#define WW   128
#define CC   256
#define GG   16
#define K2   9
#define CR   64
#define EE   144          // K2*G
#define BN_EPS 1e-3f

#define OUT1 (BB*HH*WW*CC)   // 16,777,216
#define OUT2 (BB*HH*WW*EE)   //  9,437,184

// ---------------- Kernel B: fused GEMM1 + BN + ReLU + GEMM2 -> ker ----------------
// Block = 1 image row (128 px), 256 threads, 4 blocks/SM.
// Dynamic smem layout (floats):
//   regionA [0, 8704):    xs (128 x 65, px-major) during phase 1,
//                         then hbuf (128 x 68, px-major) for phase 2
//   regionB [8704, 13312): w1 chunk (64 x 64) during phase 1,
//                          w2 chunk (32 x 144) during phase 2
#define XS_PAD 65
#define HB_PAD 68
#define SMEM_B_FLOATS 13312
#define SMEM_B_BYTES  (SMEM_B_FLOATS * 4)

__global__ void __launch_bounds__(256, 4)
invo_kergen(const float* __restrict__ x,
            const float* __restrict__ w1,
            const float* __restrict__ b1,
            const float* __restrict__ gamma,
            const float* __restrict__ beta,
            const float* __restrict__ bn_mean,
            const float* __restrict__ bn_var,
            const float* __restrict__ w2,
            const float* __restrict__ b2,
            float* __restrict__ ker_out)
{
    extern __shared__ float smem[];
    float* regionA = smem;          // xs / hbuf
    float* regionB = smem + 8704;   // w1s / w2s

    const int t   = threadIdx.x;          // 0..255
    const int bid = blockIdx.x;           // 0..511 (= b*128 + h)
    const int rowbase = bid * (WW * CC);  // x offset of this row

    // ---------------- Phase 1: h = ReLU(BN(x @ w1 + b1)) ----------------
    // Thread tile: 4 px x 8 d  (d = {4*dg..4*dg+3} U {32+4*dg..32+4*dg+3})
    const int pg    = t >> 3;        // 0..31
    const int dg    = t & 7;         // 0..7
    const int pbase = pg * 4;
    const int dA    = dg * 4;
    const int dB    = 32 + dg * 4;

    float acc[4][8];
#pragma unroll
    for (int p = 0; p < 4; ++p)
#pragma unroll
        for (int i = 0; i < 8; ++i) acc[p][i] = 0.f;

    for (int kc = 0; kc < CC; kc += 64) {
        // stage xs: 128 px x 64 j  (px-major, pad 65)
#pragma unroll
        for (int r = 0; r < 8; ++r) {
            const int i4 = t + 256 * r;          // 0..2047 float4 slots
            const int px = i4 >> 4, jq = i4 & 15;
            const float4 v = *(const float4*)&x[rowbase + px * CC + kc + jq * 4];
            float* dp = &regionA[px * XS_PAD + jq * 4];
            dp[0] = v.x; dp[1] = v.y; dp[2] = v.z; dp[3] = v.w;
        }
        // stage w1 chunk: 64 x 64
#pragma unroll
        for (int r = 0; r < 4; ++r) {
            const int i4 = t + 256 * r;          // 0..1023 float4 slots
            const int rr = i4 >> 4, cq = i4 & 15;
            *(float4*)&regionB[rr * 64 + cq * 4] =
                *(const float4*)&w1[(kc + rr) * CR + cq * 4];
        }
        __syncthreads();

#pragma unroll 4
        for (int j = 0; j < 64; ++j) {
            const float xv0 = regionA[(pbase + 0) * XS_PAD + j];
            const float xv1 = regionA[(pbase + 1) * XS_PAD + j];
            const float xv2 = regionA[(pbase + 2) * XS_PAD + j];
            const float xv3 = regionA[(pbase + 3) * XS_PAD + j];
            const float4 wa = *(const float4*)&regionB[j * 64 + dA];
            const float4 wb = *(const float4*)&regionB[j * 64 + dB];
            acc[0][0] += xv0 * wa.x; acc[0][1] += xv0 * wa.y;
            acc[0][2] += xv0 * wa.z; acc[0][3] += xv0 * wa.w;
            acc[0][4] += xv0 * wb.x; acc[0][5] += xv0 * wb.y;
            acc[0][6] += xv0 * wb.z; acc[0][7] += xv0 * wb.w;
            acc[1][0] += xv1 * wa.x; acc[1][1] += xv1 * wa.y;
            acc[1][2] += xv1 * wa.z; acc[1][3] += xv1 * wa.w;
            acc[1][4] += xv1 * wb.x; acc[1][5] += xv1 * wb.y;
            acc[1][6] += xv1 * wb.z; acc[1][7] += xv1 * wb.w;
            acc[2][0] += xv2 * wa.x; acc[2][1] += xv2 * wa.y;
            acc[2][2] += xv2 * wa.z; acc[2][3] += xv2 * wa.w;
            acc[2][4] += xv2 * wb.x; acc[2][5] += xv2 * wb.y;
            acc[2][6] += xv2 * wb.z; acc[2][7] += xv2 * wb.w;
            acc[3][0] += xv3 * wa.x; acc[3][1] += xv3 * wa.y;
            acc[3][2] += xv3 * wa.z; acc[3][3] += xv3 * wa.w;
            acc[3][4] += xv3 * wb.x; acc[3][5] += xv3 * wb.y;
            acc[3][6] += xv3 * wb.z; acc[3][7] += xv3 * wb.w;
        }
        __syncthreads();
    }

    // BN (inference) + ReLU -> hbuf (regionA, pad 68), float4 stores
#pragma unroll
    for (int m = 0; m < 2; ++m) {
        const int d0 = m ? dB : dA;
        float s[4], sh[4];
#pragma unroll
        for (int i = 0; i < 4; ++i) {
            const int d = d0 + i;
            s[i]  = gamma[d] * rsqrtf(bn_var[d] + BN_EPS);
            sh[i] = beta[d] + (b1[d] - bn_mean[d]) * s[i];
        }
#pragma unroll
        for (int p = 0; p < 4; ++p) {
            float4 v;
            v.x = fmaxf(acc[p][m * 4 + 0] * s[0] + sh[0], 0.f);
            v.y = fmaxf(acc[p][m * 4 + 1] * s[1] + sh[1], 0.f);
            v.z = fmaxf(acc[p][m * 4 + 2] * s[2] + sh[2], 0.f);
            v.w = fmaxf(acc[p][m * 4 + 3] * s[3] + sh[3], 0.f);
            *(float4*)&regionA[(pbase + p) * HB_PAD + d0] = v;
        }
    }

    // ---------------- Phase 2: ker = h @ w2 + b2 ----------------
    // Thread tile: 2 px x 18 e, two reps cover 128 px. w2 staged in 32-row chunks.
    const int eg  = t & 7;
    const int e0  = eg * 18;
    const int pg2 = t >> 3;

#pragma unroll 1
    for (int rep = 0; rep < 2; ++rep) {
        const int pb = (pg2 + 32 * rep) * 2;
        float a0[18], a1[18];
#pragma unroll
        for (int i = 0; i < 18; ++i) { a0[i] = 0.f; a1[i] = 0.f; }

#pragma unroll 1
        for (int jc = 0; jc < 64; jc += 32) {
            __syncthreads();   // protects hbuf write (first pass) / regionB reuse
#pragma unroll
            for (int r = 0; r < 18; ++r) {
                const int idx = t + 256 * r;     // 0..4607
                regionB[idx] = w2[jc * 144 + idx];
            }
            __syncthreads();

#pragma unroll 2
            for (int jr = 0; jr < 32; ++jr) {
                const int j = jc + jr;
                const float h0 = regionA[pb * HB_PAD + j];
                const float h1 = regionA[(pb + 1) * HB_PAD + j];
#pragma unroll
                for (int m = 0; m < 9; ++m) {
                    const float2 wv = *(const float2*)&regionB[jr * 144 + e0 + 2 * m];
                    a0[2 * m]     += h0 * wv.x;
                    a0[2 * m + 1] += h0 * wv.y;
                    a1[2 * m]     += h1 * wv.x;
                    a1[2 * m + 1] += h1 * wv.y;
                }
            }
        }

        const int gbase = bid * (WW * EE) + pb * EE;
#pragma unroll
        for (int m = 0; m < 9; ++m) {
            const float2 bb = *(const float2*)&b2[e0 + 2 * m];
            float2 v0, v1;
            v0.x = a0[2 * m] + bb.x;     v0.y = a0[2 * m + 1] + bb.y;
            v1.x = a1[2 * m] + bb.x;     v1.y = a1[2 * m + 1] + bb.y;
            *(float2*)&ker_out[gbase + e0 + 2 * m]      = v0;
            *(float2*)&ker_out[gbase + EE + e0 + 2 * m] = v1;
        }
    }
}

// ---------------- Kernel C: involution apply ----------------
// Block = 32 px of one row, 256 threads (= channels). ker tile in smem,
// x via sliding 3x3 register window (3 LDG per output pixel).
__global__ void __launch_bounds__(256)
invo_apply(const float* __restrict__ x,
           const float* __restrict__ ker,
           float* __restrict__ out)
{
    __shared__ float ks[32 * EE];   // 18,432 B

    const int bid = blockIdx.x;      // ((b*128 + h)*4 + wt)
    const int wt  = bid & 3;
    const int h   = (bid >> 2) & 127;
    const int b   = bid >> 9;
    const int t   = threadIdx.x;     // channel
    const int g   = t & 15;
    const int w0  = wt * 32;

    const int kbase = ((b * HH + h) * WW + w0) * EE;
#pragma unroll
    for (int r = 0; r < 18; ++r) {
        const int idx = t + 256 * r;
        ks[idx] = ker[kbase + idx];
    }
    __syncthreads();

    const float* xm = x + ((b * HH + h) * WW) * CC + t;
    const float* xu = xm - WW * CC;
    const float* xd = xm + WW * CC;
    const bool up_ok = (h > 0);
    const bool dn_ok = (h < HH - 1);
    float* op = out + ((b * HH + h) * WW + w0) * CC + t;

    float uL = 0.f, uM = 0.f, mL = 0.f, mM = 0.f, dL = 0.f, dM = 0.f;
    if (w0 > 0) {
        const int o = (w0 - 1) * CC;
        if (up_ok) uL = xu[o];
        mL = xm[o];
        if (dn_ok) dL = xd[o];
    }
    {
        const int o = w0 * CC;
        if (up_ok) uM = xu[o];
        mM = xm[o];
        if (dn_ok) dM = xd[o];
    }

#pragma unroll 8
    for (int i = 0; i < 32; ++i) {
        const int wr = w0 + i + 1;
        const bool rok = (wr < WW);
        float uR = 0.f, mR = 0.f, dR = 0.f;
        if (rok) {
            const int o = wr * CC;
            if (up_ok) uR = xu[o];
            mR = xm[o];
            if (dn_ok) dR = xd[o];
        }
        const float* kk = &ks[i * EE + g];
        float a;
        a  = uL * kk[0 * 16];
        a += uM * kk[1 * 16];
        a += uR * kk[2 * 16];
        a += mL * kk[3 * 16];
        a += mM * kk[4 * 16];
        a += mR * kk[5 * 16];
        a += dL * kk[6 * 16];
        a += dM * kk[7 * 16];
        a += dR * kk[8 * 16];
        op[i * CC] = a;

        uL = uM; uM = uR;
        mL = mM; mM = mR;
        dL = dM; dM = dR;
    }
}

extern "C" void kernel_launch(void* const* d_in, const int* in_sizes, int n_in,
                              void* d_out, int out_size) {
    const float* x       = (const float*)d_in[0];
    const float* w1      = (const float*)d_in[1];
    const float* b1      = (const float*)d_in[2];
    const float* gamma   = (const float*)d_in[3];
    const float* beta    = (const float*)d_in[4];
    const float* bn_mean = (const float*)d_in[5];
    const float* bn_var  = (const float*)d_in[6];
    const float* w2      = (const float*)d_in[7];
    const float* b2      = (const float*)d_in[8];

    float* out     = (float*)d_out;
    float* ker_out = out + OUT1;   // verified: out_size >= OUT1 + OUT2

    static bool configured = false;
    if (!configured) {
        cudaFuncSetAttribute(invo_kergen,
                             cudaFuncAttributeMaxDynamicSharedMemorySize,
                             SMEM_B_BYTES);
        configured = true;
    }

    invo_kergen<<<BB * HH, 256, SMEM_B_BYTES>>>(
        x, w1, b1, gamma, beta, bn_mean, bn_var, w2, b2, ker_out);

    invo_apply<<<BB * HH * 4, 256>>>(x, ker_out, out);
}

// round 4
// speedup vs baseline: 3.9650x; 1.3199x over previous
#include <cuda_runtime.h>

#define BB   4
#define HH   128
#define WW   128
#define CC   256
#define GG   16
#define K2   9
#define CR   64
#define EE   144
#define BN_EPS 1e-3f

#define NPX  (BB*HH*WW)      // 65536 pixels
#define OUT1 (NPX*CC)        // 16,777,216
#define OUT2 (NPX*EE)        //  9,437,184

// Scratch for intermediate h = ReLU(BN(x@w1+b1)):  65536 x 64 fp32
__device__ float g_h[NPX * CR];

// ---------------------------------------------------------------------------
// tf32 helpers
// ---------------------------------------------------------------------------
__device__ __forceinline__ unsigned f2tf32(float f) {
    unsigned r;
    asm("cvt.rna.tf32.f32 %0, %1;" : "=r"(r) : "f"(f));
    return r;
}

__device__ __forceinline__ void split_tf32(float v, unsigned& hi, unsigned& lo) {
    hi = f2tf32(v);
    float hf = __uint_as_float(hi);
    lo = f2tf32(v - hf);
}

__device__ __forceinline__ void mma_tf32(float c[4], const unsigned a[4],
                                         const unsigned b0, const unsigned b1) {
    asm("mma.sync.aligned.m16n8k8.row.col.f32.tf32.tf32.f32 "
        "{%0,%1,%2,%3}, {%4,%5,%6,%7}, {%8,%9}, {%0,%1,%2,%3};"
        : "+f"(c[0]), "+f"(c[1]), "+f"(c[2]), "+f"(c[3])
        : "r"(a[0]), "r"(a[1]), "r"(a[2]), "r"(a[3]), "r"(b0), "r"(b1));
}

// ---------------------------------------------------------------------------
// g1: h = ReLU(BN(x @ w1 + b1))    M=65536, N=64, K=256
// Block = 128 px, 256 threads (8 warps). Warp tile: 2 m-tiles x 4 n-tiles.
// ---------------------------------------------------------------------------
#define XS_STR 36     // 32 + 4 pad  (stride%32==4 -> A frags conflict-free)
#define W1_STR 72     // 64 + 8 pad  (stride%32==8 -> B frags conflict-free)

__global__ void __launch_bounds__(256, 2)
g1_kernel(const float* __restrict__ x,
          const float* __restrict__ w1,
          const float* __restrict__ b1,
          const float* __restrict__ gamma,
          const float* __restrict__ beta,
          const float* __restrict__ bn_mean,
          const float* __restrict__ bn_var)
{
    __shared__ float xs[128 * XS_STR];   // 18,432 B
    __shared__ float w1s[32 * W1_STR];   //  9,216 B

    const int t    = threadIdx.x;
    const int warp = t >> 5;
    const int lane = t & 31;
    const int gid  = lane >> 2;
    const int tg   = lane & 3;
    const int px0  = (warp & 3) * 32;     // warp m-base (2 m-tiles: +0, +16)
    const int nb   = (warp >> 2) * 32;    // warp n-base (4 n-tiles of 8)

    const int rowbase = blockIdx.x * (128 * CC);

    float c[2][4][4];
#pragma unroll
    for (int mt = 0; mt < 2; ++mt)
#pragma unroll
        for (int nt = 0; nt < 4; ++nt)
#pragma unroll
            for (int i = 0; i < 4; ++i) c[mt][nt][i] = 0.f;

    for (int kc = 0; kc < CC; kc += 32) {
        // stage x tile: 128 px x 32 k
#pragma unroll
        for (int r = 0; r < 4; ++r) {
            const int i4 = t + 256 * r;       // float4 index
            const int px = i4 >> 3, kq = i4 & 7;
            const float4 v = *(const float4*)&x[rowbase + px * CC + kc + kq * 4];
            *(float4*)&xs[px * XS_STR + kq * 4] = v;
        }
        // stage w1 tile: 32 k x 64 n
#pragma unroll
        for (int r = 0; r < 2; ++r) {
            const int i4 = t + 256 * r;
            const int row = i4 >> 4, cq = i4 & 15;
            const float4 v = *(const float4*)&w1[(kc + row) * CR + cq * 4];
            *(float4*)&w1s[row * W1_STR + cq * 4] = v;
        }
        __syncthreads();

#pragma unroll
        for (int ks = 0; ks < 4; ++ks) {
            const int koff = ks * 8;
            // B fragments (4 n-tiles), split hi/lo
            unsigned bhi[4][2], blo[4][2];
#pragma unroll
            for (int nt = 0; nt < 4; ++nt) {
                const float b0 = w1s[(koff + tg) * W1_STR + nb + nt * 8 + gid];
                const float b1v = w1s[(koff + tg + 4) * W1_STR + nb + nt * 8 + gid];
                split_tf32(b0, bhi[nt][0], blo[nt][0]);
                split_tf32(b1v, bhi[nt][1], blo[nt][1]);
            }
#pragma unroll
            for (int mt = 0; mt < 2; ++mt) {
                const int pr = px0 + mt * 16 + gid;
                float a0 = xs[pr * XS_STR + koff + tg];
                float a1 = xs[(pr + 8) * XS_STR + koff + tg];
                float a2 = xs[pr * XS_STR + koff + tg + 4];
                float a3 = xs[(pr + 8) * XS_STR + koff + tg + 4];
                unsigned ahi[4], alo[4];
                split_tf32(a0, ahi[0], alo[0]);
                split_tf32(a1, ahi[1], alo[1]);
                split_tf32(a2, ahi[2], alo[2]);
                split_tf32(a3, ahi[3], alo[3]);
#pragma unroll
                for (int nt = 0; nt < 4; ++nt) {
                    mma_tf32(c[mt][nt], ahi, bhi[nt][0], bhi[nt][1]);
                    mma_tf32(c[mt][nt], ahi, blo[nt][0], blo[nt][1]);
                    mma_tf32(c[mt][nt], alo, bhi[nt][0], bhi[nt][1]);
                }
            }
        }
        __syncthreads();
    }

    // epilogue: BN + ReLU -> g_h
#pragma unroll
    for (int nt = 0; nt < 4; ++nt) {
        const int d0 = nb + nt * 8 + 2 * tg;
        const int d1 = d0 + 1;
        const float s0  = gamma[d0] * rsqrtf(bn_var[d0] + BN_EPS);
        const float s1  = gamma[d1] * rsqrtf(bn_var[d1] + BN_EPS);
        const float sh0 = beta[d0] + (b1[d0] - bn_mean[d0]) * s0;
        const float sh1 = beta[d1] + (b1[d1] - bn_mean[d1]) * s1;
#pragma unroll
        for (int mt = 0; mt < 2; ++mt) {
            const int r0 = blockIdx.x * 128 + px0 + mt * 16 + gid;
            const int r1 = r0 + 8;
            float2 v0, v1;
            v0.x = fmaxf(c[mt][nt][0] * s0 + sh0, 0.f);
            v0.y = fmaxf(c[mt][nt][1] * s1 + sh1, 0.f);
            v1.x = fmaxf(c[mt][nt][2] * s0 + sh0, 0.f);
            v1.y = fmaxf(c[mt][nt][3] * s1 + sh1, 0.f);
            *(float2*)&g_h[r0 * CR + d0] = v0;
            *(float2*)&g_h[r1 * CR + d0] = v1;
        }
    }
}

// ---------------------------------------------------------------------------
// g2: ker = h @ w2 + b2    M=65536, N=144, K=64
// Block = 128 px, 256 threads (8 warps). Warp tile: 2 m-tiles x 9 n-tiles.
// ---------------------------------------------------------------------------
#define HS_STR 68     // 64 + 4 pad  (stride%32==4)
#define W2_STR 168    // 144 + 24 pad (stride%32==8)
#define G2_SMEM_BYTES ((128 * HS_STR + 64 * W2_STR) * 4)   // 77,824 B

__global__ void __launch_bounds__(256)
g2_kernel(const float* __restrict__ w2,
          const float* __restrict__ b2,
          float* __restrict__ ker_out)
{
    extern __shared__ float smem[];
    float* hs  = smem;                   // 128 x 68
    float* w2s = smem + 128 * HS_STR;    // 64 x 168

    const int t    = threadIdx.x;
    const int warp = t >> 5;
    const int lane = t & 31;
    const int gid  = lane >> 2;
    const int tg   = lane & 3;
    const int px0  = (warp & 3) * 32;
    const int nbase = (warp >> 2) * 72;   // 9 n-tiles of 8

    // stage h tile: 128 x 64
    const int hbase = blockIdx.x * (128 * CR);
#pragma unroll
    for (int r = 0; r < 8; ++r) {
        const int i4 = t + 256 * r;
        const int px = i4 >> 4, kq = i4 & 15;
        const float4 v = *(const float4*)&g_h[hbase + px * CR + kq * 4];
        *(float4*)&hs[px * HS_STR + kq * 4] = v;
    }
    // stage w2: 64 x 144
#pragma unroll
    for (int r = 0; r < 9; ++r) {
        const int i4 = t + 256 * r;       // 0..2303
        const int row = i4 / 36, cq = i4 - row * 36;
        const float4 v = *(const float4*)&w2[row * EE + cq * 4];
        *(float4*)&w2s[row * W2_STR + cq * 4] = v;
    }
    __syncthreads();

    float c[2][9][4];
#pragma unroll
    for (int mt = 0; mt < 2; ++mt)
#pragma unroll
        for (int nt = 0; nt < 9; ++nt)
#pragma unroll
            for (int i = 0; i < 4; ++i) c[mt][nt][i] = 0.f;

#pragma unroll
    for (int ks = 0; ks < 8; ++ks) {
        const int koff = ks * 8;
        unsigned bhi[9][2], blo[9][2];
#pragma unroll
        for (int nt = 0; nt < 9; ++nt) {
            const float b0 = w2s[(koff + tg) * W2_STR + nbase + nt * 8 + gid];
            const float b1v = w2s[(koff + tg + 4) * W2_STR + nbase + nt * 8 + gid];
            split_tf32(b0, bhi[nt][0], blo[nt][0]);
            split_tf32(b1v, bhi[nt][1], blo[nt][1]);
        }
#pragma unroll
        for (int mt = 0; mt < 2; ++mt) {
            const int pr = px0 + mt * 16 + gid;
            float a0 = hs[pr * HS_STR + koff + tg];
            float a1 = hs[(pr + 8) * HS_STR + koff + tg];
            float a2 = hs[pr * HS_STR + koff + tg + 4];
            float a3 = hs[(pr + 8) * HS_STR + koff + tg + 4];
            unsigned ahi[4], alo[4];
            split_tf32(a0, ahi[0], alo[0]);
            split_tf32(a1, ahi[1], alo[1]);
            split_tf32(a2, ahi[2], alo[2]);
            split_tf32(a3, ahi[3], alo[3]);
#pragma unroll
            for (int nt = 0; nt < 9; ++nt) {
                mma_tf32(c[mt][nt], ahi, bhi[nt][0], bhi[nt][1]);
                mma_tf32(c[mt][nt], ahi, blo[nt][0], blo[nt][1]);
                mma_tf32(c[mt][nt], alo, bhi[nt][0], bhi[nt][1]);
            }
        }
    }

    // epilogue: + b2 -> ker_out
#pragma unroll
    for (int nt = 0; nt < 9; ++nt) {
        const int e0 = nbase + nt * 8 + 2 * tg;
        const float2 bb = *(const float2*)&b2[e0];
#pragma unroll
        for (int mt = 0; mt < 2; ++mt) {
            const int r0 = blockIdx.x * 128 + px0 + mt * 16 + gid;
            const int r1 = r0 + 8;
            float2 v0, v1;
            v0.x = c[mt][nt][0] + bb.x;
            v0.y = c[mt][nt][1] + bb.y;
            v1.x = c[mt][nt][2] + bb.x;
            v1.y = c[mt][nt][3] + bb.y;
            *(float2*)&ker_out[r0 * EE + e0] = v0;
            *(float2*)&ker_out[r1 * EE + e0] = v1;
        }
    }
}

// ---------------------------------------------------------------------------
// Kernel C: involution apply (unchanged — measured 42.8us)
// ---------------------------------------------------------------------------
__global__ void __launch_bounds__(256)
invo_apply(const float* __restrict__ x,
           const float* __restrict__ ker,
           float* __restrict__ out)
{
    __shared__ float ks[32 * EE];

    const int bid = blockIdx.x;
    const int wt  = bid & 3;
    const int h   = (bid >> 2) & 127;
    const int b   = bid >> 9;
    const int t   = threadIdx.x;
    const int g   = t & 15;
    const int w0  = wt * 32;

    const int kbase = ((b * HH + h) * WW + w0) * EE;
#pragma unroll
    for (int r = 0; r < 18; ++r) {
        const int idx = t + 256 * r;
        ks[idx] = ker[kbase + idx];
    }
    __syncthreads();

    const float* xm = x + ((b * HH + h) * WW) * CC + t;
    const float* xu = xm - WW * CC;
    const float* xd = xm + WW * CC;
    const bool up_ok = (h > 0);
    const bool dn_ok = (h < HH - 1);
    float* op = out + ((b * HH + h) * WW + w0) * CC + t;

    float uL = 0.f, uM = 0.f, mL = 0.f, mM = 0.f, dL = 0.f, dM = 0.f;
    if (w0 > 0) {
        const int o = (w0 - 1) * CC;
        if (up_ok) uL = xu[o];
        mL = xm[o];
        if (dn_ok) dL = xd[o];
    }
    {
        const int o = w0 * CC;
        if (up_ok) uM = xu[o];
        mM = xm[o];
        if (dn_ok) dM = xd[o];
    }

#pragma unroll 8
    for (int i = 0; i < 32; ++i) {
        const int wr = w0 + i + 1;
        const bool rok = (wr < WW);
        float uR = 0.f, mR = 0.f, dR = 0.f;
        if (rok) {
            const int o = wr * CC;
            if (up_ok) uR = xu[o];
            mR = xm[o];
            if (dn_ok) dR = xd[o];
        }
        const float* kk = &ks[i * EE + g];
        float a;
        a  = uL * kk[0 * 16];
        a += uM * kk[1 * 16];
        a += uR * kk[2 * 16];
        a += mL * kk[3 * 16];
        a += mM * kk[4 * 16];
        a += mR * kk[5 * 16];
        a += dL * kk[6 * 16];
        a += dM * kk[7 * 16];
        a += dR * kk[8 * 16];
        op[i * CC] = a;

        uL = uM; uM = uR;
        mL = mM; mM = mR;
        dL = dM; dM = dR;
    }
}

extern "C" void kernel_launch(void* const* d_in, const int* in_sizes, int n_in,
                              void* d_out, int out_size) {
    const float* x       = (const float*)d_in[0];
    const float* w1      = (const float*)d_in[1];
    const float* b1      = (const float*)d_in[2];
    const float* gamma   = (const float*)d_in[3];
    const float* beta    = (const float*)d_in[4];
    const float* bn_mean = (const float*)d_in[5];
    const float* bn_var  = (const float*)d_in[6];
    const float* w2      = (const float*)d_in[7];
    const float* b2      = (const float*)d_in[8];

    float* out     = (float*)d_out;
    float* ker_out = out + OUT1;

    // Idempotent host-side attribute set (no static guards).
    cudaFuncSetAttribute(g2_kernel,
                         cudaFuncAttributeMaxDynamicSharedMemorySize,
                         G2_SMEM_BYTES);

    g1_kernel<<<NPX / 128, 256>>>(x, w1, b1, gamma, beta, bn_mean, bn_var);
    g2_kernel<<<NPX / 128, 256, G2_SMEM_BYTES>>>(w2, b2, ker_out);
    invo_apply<<<BB * HH * 4, 256>>>(x, ker_out, out);
}

// round 5
// speedup vs baseline: 4.4942x; 1.1335x over previous
#include <cuda_runtime.h>

#define BB   4
#define HH   128
#define WW   128
#define CC   256
#define GG   16
#define K2   9
#define CR   64
#define EE   144
#define BN_EPS 1e-3f

#define NPX  (BB*HH*WW)      // 65536 pixels
#define OUT1 (NPX*CC)        // 16,777,216
#define OUT2 (NPX*EE)        //  9,437,184

// Intermediate h = ReLU(BN(x@w1+b1)), stored pre-split as packed bf16x2.
// 65536 px x 32 k-pairs per array (k-pair = 2 consecutive of CR=64 channels).
__device__ unsigned g_h_hi[NPX * 32];
__device__ unsigned g_h_lo[NPX * 32];

// ---------------------------------------------------------------------------
// bf16 helpers
// ---------------------------------------------------------------------------
// Pack (f_even, f_odd) into bf16x2 hi part + bf16x2 residual (lo) part.
// u32 layout: low 16 bits = even-k element (mma convention).
__device__ __forceinline__ void pack_split(float fe, float fo,
                                           unsigned& hi, unsigned& lo) {
    unsigned h;
    asm("cvt.rn.bf16x2.f32 %0, %1, %2;" : "=r"(h) : "f"(fo), "f"(fe));
    const float he = __uint_as_float(h << 16);
    const float ho = __uint_as_float(h & 0xffff0000u);
    const float re = fe - he;
    const float ro = fo - ho;
    unsigned l;
    asm("cvt.rn.bf16x2.f32 %0, %1, %2;" : "=r"(l) : "f"(ro), "f"(re));
    hi = h; lo = l;
}

__device__ __forceinline__ void mma_bf16(float c[4], const unsigned a[4],
                                         const unsigned b0, const unsigned b1) {
    asm("mma.sync.aligned.m16n8k16.row.col.f32.bf16.bf16.f32 "
        "{%0,%1,%2,%3}, {%4,%5,%6,%7}, {%8,%9}, {%0,%1,%2,%3};"
        : "+f"(c[0]), "+f"(c[1]), "+f"(c[2]), "+f"(c[3])
        : "r"(a[0]), "r"(a[1]), "r"(a[2]), "r"(a[3]), "r"(b0), "r"(b1));
}

// ---------------------------------------------------------------------------
// g1: h = ReLU(BN(x @ w1 + b1))    M=65536, N=64, K=256
// Block = 128 px, 256 threads (8 warps). Warp: 2 m-tiles x 4 n-tiles.
// K staged in chunks of 32 (16 k-pairs), pre-split bf16 in smem.
// ---------------------------------------------------------------------------
#define XS_S 20    // u32 stride/px row: 16 kp + 4 pad (20%32==20; 20*gid+tg distinct)
#define W1_T 72    // u32 stride/kp row: 64 n + 8 pad  (72%32==8 -> 8*tg+gid distinct)

__global__ void __launch_bounds__(256, 3)
g1_kernel(const float* __restrict__ x,
          const float* __restrict__ w1,
          const float* __restrict__ b1,
          const float* __restrict__ gamma,
          const float* __restrict__ beta,
          const float* __restrict__ bn_mean,
          const float* __restrict__ bn_var)
{
    __shared__ unsigned xs_hi[128 * XS_S];   // 10,240 B
    __shared__ unsigned xs_lo[128 * XS_S];
    __shared__ unsigned w1s_hi[16 * W1_T];   //  4,608 B
    __shared__ unsigned w1s_lo[16 * W1_T];

    const int t    = threadIdx.x;
    const int warp = t >> 5;
    const int lane = t & 31;
    const int gid  = lane >> 2;
    const int tg   = lane & 3;
    const int px0  = (warp & 3) * 32;
    const int nb   = (warp >> 2) * 32;

    const int rowbase = blockIdx.x * (128 * CC);

    float c[2][4][4];
#pragma unroll
    for (int mt = 0; mt < 2; ++mt)
#pragma unroll
        for (int nt = 0; nt < 4; ++nt)
#pragma unroll
            for (int i = 0; i < 4; ++i) c[mt][nt][i] = 0.f;

    // w1 staging assignment (constant across chunks): thread -> (kp, nq)
    const int wkp = t >> 4;    // 0..15
    const int wnq = t & 15;    // 0..15

    for (int kc = 0; kc < CC; kc += 32) {
        // --- stage x: 128 px x 32 k, split to bf16 hi/lo ---
#pragma unroll
        for (int r = 0; r < 4; ++r) {
            const int i4 = t + 256 * r;          // float4 slot
            const int px = i4 >> 3, kq = i4 & 7;
            const float4 v = *(const float4*)&x[rowbase + px * CC + kc + kq * 4];
            unsigned h0, l0, h1, l1;
            pack_split(v.x, v.y, h0, l0);
            pack_split(v.z, v.w, h1, l1);
            const int o = px * XS_S + 2 * kq;
            xs_hi[o] = h0; xs_hi[o + 1] = h1;
            xs_lo[o] = l0; xs_lo[o + 1] = l1;
        }
        // --- stage w1: 32 k x 64 n -> packed k-pairs ---
        {
            const int row0 = kc + 2 * wkp;
            const float4 va = *(const float4*)&w1[row0 * CR + wnq * 4];
            const float4 vb = *(const float4*)&w1[(row0 + 1) * CR + wnq * 4];
            uint4 hh, ll;
            pack_split(va.x, vb.x, hh.x, ll.x);
            pack_split(va.y, vb.y, hh.y, ll.y);
            pack_split(va.z, vb.z, hh.z, ll.z);
            pack_split(va.w, vb.w, hh.w, ll.w);
            *(uint4*)&w1s_hi[wkp * W1_T + wnq * 4] = hh;
            *(uint4*)&w1s_lo[wkp * W1_T + wnq * 4] = ll;
        }
        __syncthreads();

#pragma unroll
        for (int ks = 0; ks < 2; ++ks) {
            const int base = ks * 8;            // k-pair base of this k16 step
            unsigned bh[4][2], bl[4][2];
#pragma unroll
            for (int nt = 0; nt < 4; ++nt) {
                const int col = nb + nt * 8 + gid;
                bh[nt][0] = w1s_hi[(base + tg) * W1_T + col];
                bh[nt][1] = w1s_hi[(base + tg + 4) * W1_T + col];
                bl[nt][0] = w1s_lo[(base + tg) * W1_T + col];
                bl[nt][1] = w1s_lo[(base + tg + 4) * W1_T + col];
            }
#pragma unroll
            for (int mt = 0; mt < 2; ++mt) {
                const int pr = px0 + mt * 16 + gid;
                unsigned ah[4], al[4];
                ah[0] = xs_hi[pr * XS_S + base + tg];
                ah[1] = xs_hi[(pr + 8) * XS_S + base + tg];
                ah[2] = xs_hi[pr * XS_S + base + tg + 4];
                ah[3] = xs_hi[(pr + 8) * XS_S + base + tg + 4];
                al[0] = xs_lo[pr * XS_S + base + tg];
                al[1] = xs_lo[(pr + 8) * XS_S + base + tg];
                al[2] = xs_lo[pr * XS_S + base + tg + 4];
                al[3] = xs_lo[(pr + 8) * XS_S + base + tg + 4];
#pragma unroll
                for (int nt = 0; nt < 4; ++nt) {
                    mma_bf16(c[mt][nt], ah, bh[nt][0], bh[nt][1]);
                    mma_bf16(c[mt][nt], ah, bl[nt][0], bl[nt][1]);
                    mma_bf16(c[mt][nt], al, bh[nt][0], bh[nt][1]);
                }
            }
        }
        __syncthreads();
    }

    // epilogue: BN + ReLU, split to bf16, store packed hi/lo to g_h
#pragma unroll
    for (int nt = 0; nt < 4; ++nt) {
        const int d0 = nb + nt * 8 + 2 * tg;
        const int d1 = d0 + 1;
        const float s0  = gamma[d0] * rsqrtf(bn_var[d0] + BN_EPS);
        const float s1  = gamma[d1] * rsqrtf(bn_var[d1] + BN_EPS);
        const float sh0 = beta[d0] + (b1[d0] - bn_mean[d0]) * s0;
        const float sh1 = beta[d1] + (b1[d1] - bn_mean[d1]) * s1;
        const int kp = (nb >> 1) + nt * 4 + tg;   // k-pair index = d0/2
#pragma unroll
        for (int mt = 0; mt < 2; ++mt) {
            const int r0 = blockIdx.x * 128 + px0 + mt * 16 + gid;
            const int r1 = r0 + 8;
            const float v0e = fmaxf(c[mt][nt][0] * s0 + sh0, 0.f);
            const float v0o = fmaxf(c[mt][nt][1] * s1 + sh1, 0.f);
            const float v1e = fmaxf(c[mt][nt][2] * s0 + sh0, 0.f);
            const float v1o = fmaxf(c[mt][nt][3] * s1 + sh1, 0.f);
            unsigned h0, l0, h1, l1;
            pack_split(v0e, v0o, h0, l0);
            pack_split(v1e, v1o, h1, l1);
            g_h_hi[r0 * 32 + kp] = h0;
            g_h_lo[r0 * 32 + kp] = l0;
            g_h_hi[r1 * 32 + kp] = h1;
            g_h_lo[r1 * 32 + kp] = l1;
        }
    }
}

// ---------------------------------------------------------------------------
// g2: ker = h @ w2 + b2    M=65536, N=144, K=64
// Block = 128 px, 256 threads (8 warps). Warp: 2 m-tiles x 9 n-tiles.
// K in 2 chunks of 32 (16 k-pairs each).
// ---------------------------------------------------------------------------
#define HS_S 20
#define W2_T 168   // 144 + 24 pad (168%32==8)

__global__ void __launch_bounds__(256, 2)
g2_kernel(const float* __restrict__ w2,
          const float* __restrict__ b2,
          float* __restrict__ ker_out)
{
    __shared__ unsigned hs_hi[128 * HS_S];   // 10,240 B
    __shared__ unsigned hs_lo[128 * HS_S];
    __shared__ unsigned w2s_hi[16 * W2_T];   // 10,752 B
    __shared__ unsigned w2s_lo[16 * W2_T];

    const int t    = threadIdx.x;
    const int warp = t >> 5;
    const int lane = t & 31;
    const int gid  = lane >> 2;
    const int tg   = lane & 3;
    const int px0  = (warp & 3) * 32;
    const int nbase = (warp >> 2) * 72;

    float c[2][9][4];
#pragma unroll
    for (int mt = 0; mt < 2; ++mt)
#pragma unroll
        for (int nt = 0; nt < 9; ++nt)
#pragma unroll
            for (int i = 0; i < 4; ++i) c[mt][nt][i] = 0.f;

#pragma unroll 1
    for (int kc2 = 0; kc2 < 32; kc2 += 16) {   // k-pair chunk base
        // --- stage h (already split): pure copies ---
#pragma unroll
        for (int r = 0; r < 2; ++r) {
            const int i4 = t + 256 * r;        // uint4 slot, 0..511
            const int px = i4 >> 2, kq = i4 & 3;
            const int gidx = (blockIdx.x * 128 + px) * 32 + kc2 + kq * 4;
            *(uint4*)&hs_hi[px * HS_S + kq * 4] = *(const uint4*)&g_h_hi[gidx];
            *(uint4*)&hs_lo[px * HS_S + kq * 4] = *(const uint4*)&g_h_lo[gidx];
        }
        // --- stage w2: 32 k x 144 n -> packed k-pairs, split ---
        for (int idx = t; idx < 576; idx += 256) {
            const int kp = idx & 15;           // 0..15
            const int nq = idx >> 4;           // 0..35
            const int grow = (kc2 + kp) * 2;
            const float4 va = *(const float4*)&w2[grow * EE + nq * 4];
            const float4 vb = *(const float4*)&w2[(grow + 1) * EE + nq * 4];
            uint4 hh, ll;
            pack_split(va.x, vb.x, hh.x, ll.x);
            pack_split(va.y, vb.y, hh.y, ll.y);
            pack_split(va.z, vb.z, hh.z, ll.z);
            pack_split(va.w, vb.w, hh.w, ll.w);
            *(uint4*)&w2s_hi[kp * W2_T + nq * 4] = hh;
            *(uint4*)&w2s_lo[kp * W2_T + nq * 4] = ll;
        }
        __syncthreads();

#pragma unroll
        for (int ks = 0; ks < 2; ++ks) {
            const int base = ks * 8;
#pragma unroll
            for (int mt = 0; mt < 2; ++mt) {
                const int pr = px0 + mt * 16 + gid;
                unsigned ah[4], al[4];
                ah[0] = hs_hi[pr * HS_S + base + tg];
                ah[1] = hs_hi[(pr + 8) * HS_S + base + tg];
                ah[2] = hs_hi[pr * HS_S + base + tg + 4];
                ah[3] = hs_hi[(pr + 8) * HS_S + base + tg + 4];
                al[0] = hs_lo[pr * HS_S + base + tg];
                al[1] = hs_lo[(pr + 8) * HS_S + base + tg];
                al[2] = hs_lo[pr * HS_S + base + tg + 4];
                al[3] = hs_lo[(pr + 8) * HS_S + base + tg + 4];
#pragma unroll
                for (int nt = 0; nt < 9; ++nt) {
                    const int col = nbase + nt * 8 + gid;
                    const unsigned bh0 = w2s_hi[(base + tg) * W2_T + col];
                    const unsigned bh1 = w2s_hi[(base + tg + 4) * W2_T + col];
                    const unsigned bl0 = w2s_lo[(base + tg) * W2_T + col];
                    const unsigned bl1 = w2s_lo[(base + tg + 4) * W2_T + col];
                    mma_bf16(c[mt][nt], ah, bh0, bh1);
                    mma_bf16(c[mt][nt], ah, bl0, bl1);
                    mma_bf16(c[mt][nt], al, bh0, bh1);
                }
            }
        }
        __syncthreads();
    }

    // epilogue: + b2 -> ker_out (fp32)
#pragma unroll
    for (int nt = 0; nt < 9; ++nt) {
        const int e0 = nbase + nt * 8 + 2 * tg;
        const float2 bb = *(const float2*)&b2[e0];
#pragma unroll
        for (int mt = 0; mt < 2; ++mt) {
            const int r0 = blockIdx.x * 128 + px0 + mt * 16 + gid;
            const int r1 = r0 + 8;
            float2 v0, v1;
            v0.x = c[mt][nt][0] + bb.x;
            v0.y = c[mt][nt][1] + bb.y;
            v1.x = c[mt][nt][2] + bb.x;
            v1.y = c[mt][nt][3] + bb.y;
            *(float2*)&ker_out[r0 * EE + e0] = v0;
            *(float2*)&ker_out[r1 * EE + e0] = v1;
        }
    }
}

// ---------------------------------------------------------------------------
// Kernel C: involution apply — 2 channels per thread (c, c+128 share group g)
// Block = 32 px of one row, 128 threads.
// ---------------------------------------------------------------------------
__global__ void __launch_bounds__(128)
invo_apply(const float* __restrict__ x,
           const float* __restrict__ ker,
           float* __restrict__ out)
{
    __shared__ float ks[32 * EE];   // 18,432 B

    const int bid = blockIdx.x;      // ((b*128 + h)*4 + wt)
    const int wt  = bid & 3;
    const int h   = (bid >> 2) & 127;
    const int b   = bid >> 9;
    const int t   = threadIdx.x;     // 0..127, channel c = t (and c+128)
    const int g   = t & 15;
    const int w0  = wt * 32;

    const int kbase = ((b * HH + h) * WW + w0) * EE;
#pragma unroll
    for (int r = 0; r < 36; ++r) {
        const int idx = t + 128 * r;
        ks[idx] = ker[kbase + idx];
    }
    __syncthreads();

    const float* xm = x + ((b * HH + h) * WW) * CC + t;
    const float* xu = xm - WW * CC;
    const float* xd = xm + WW * CC;
    const bool up_ok = (h > 0);
    const bool dn_ok = (h < HH - 1);
    float* op = out + ((b * HH + h) * WW + w0) * CC + t;

    // sliding windows for channel c (suffix A) and c+128 (suffix B)
    float uLa = 0.f, uMa = 0.f, mLa = 0.f, mMa = 0.f, dLa = 0.f, dMa = 0.f;
    float uLb = 0.f, uMb = 0.f, mLb = 0.f, mMb = 0.f, dLb = 0.f, dMb = 0.f;
    if (w0 > 0) {
        const int o = (w0 - 1) * CC;
        if (up_ok) { uLa = xu[o]; uLb = xu[o + 128]; }
        mLa = xm[o]; mLb = xm[o + 128];
        if (dn_ok) { dLa = xd[o]; dLb = xd[o + 128]; }
    }
    {
        const int o = w0 * CC;
        if (up_ok) { uMa = xu[o]; uMb = xu[o + 128]; }
        mMa = xm[o]; mMb = xm[o + 128];
        if (dn_ok) { dMa = xd[o]; dMb = xd[o + 128]; }
    }

#pragma unroll 4
    for (int i = 0; i < 32; ++i) {
        const int wr = w0 + i + 1;
        const bool rok = (wr < WW);
        float uRa = 0.f, mRa = 0.f, dRa = 0.f;
        float uRb = 0.f, mRb = 0.f, dRb = 0.f;
        if (rok) {
            const int o = wr * CC;
            if (up_ok) { uRa = xu[o]; uRb = xu[o + 128]; }
            mRa = xm[o]; mRb = xm[o + 128];
            if (dn_ok) { dRa = xd[o]; dRb = xd[o + 128]; }
        }
        const float* kk = &ks[i * EE + g];
        const float k0 = kk[0 * 16], k1 = kk[1 * 16], k2 = kk[2 * 16];
        const float k3 = kk[3 * 16], k4 = kk[4 * 16], k5 = kk[5 * 16];
        const float k6 = kk[6 * 16], k7 = kk[7 * 16], k8 = kk[8 * 16];

        float a = uLa * k0 + uMa * k1 + uRa * k2
                + mLa * k3 + mMa * k4 + mRa * k5
                + dLa * k6 + dMa * k7 + dRa * k8;
        float bv = uLb * k0 + uMb * k1 + uRb * k2
                 + mLb * k3 + mMb * k4 + mRb * k5
                 + dLb * k6 + dMb * k7 + dRb * k8;
        op[i * CC] = a;
        op[i * CC + 128] = bv;

        uLa = uMa; uMa = uRa; mLa = mMa; mMa = mRa; dLa = dMa; dMa = dRa;
        uLb = uMb; uMb = uRb; mLb = mMb; mMb = mRb; dLb = dMb; dMb = dRb;
    }
}

extern "C" void kernel_launch(void* const* d_in, const int* in_sizes, int n_in,
                              void* d_out, int out_size) {
    const float* x       = (const float*)d_in[0];
    const float* w1      = (const float*)d_in[1];
    const float* b1      = (const float*)d_in[2];
    const float* gamma   = (const float*)d_in[3];
    const float* beta    = (const float*)d_in[4];
    const float* bn_mean = (const float*)d_in[5];
    const float* bn_var  = (const float*)d_in[6];
    const float* w2      = (const float*)d_in[7];
    const float* b2      = (const float*)d_in[8];

    float* out     = (float*)d_out;
    float* ker_out = out + OUT1;

    g1_kernel<<<NPX / 128, 256>>>(x, w1, b1, gamma, beta, bn_mean, bn_var);
    g2_kernel<<<NPX / 128, 256>>>(w2, b2, ker_out);
    invo_apply<<<BB * HH * 4, 128>>>(x, ker_out, out);
}

// round 7
// speedup vs baseline: 4.8281x; 1.0743x over previous
#include <cuda_runtime.h>

#define BB   4
#define HH   128
#define WW   128
#define CC   256
#define GG   16
#define CR   64
#define EE   144
#define BN_EPS 1e-3f

#define NPX  (BB*HH*WW)      // 65536 pixels
#define OUT1 (NPX*CC)        // 16,777,216

// Intermediate h = ReLU(BN(x@w1+b1)), stored pre-split as packed bf16x2.
__device__ unsigned g_h_hi[NPX * 32];
__device__ unsigned g_h_lo[NPX * 32];

// ---------------------------------------------------------------------------
// bf16 helpers
// ---------------------------------------------------------------------------
__device__ __forceinline__ void pack_split(float fe, float fo,
                                           unsigned& hi, unsigned& lo) {
    unsigned h;
    asm("cvt.rn.bf16x2.f32 %0, %1, %2;" : "=r"(h) : "f"(fo), "f"(fe));
    const float he = __uint_as_float(h << 16);
    const float ho = __uint_as_float(h & 0xffff0000u);
    const float re = fe - he;
    const float ro = fo - ho;
    unsigned l;
    asm("cvt.rn.bf16x2.f32 %0, %1, %2;" : "=r"(l) : "f"(ro), "f"(re));
    hi = h; lo = l;
}

__device__ __forceinline__ void mma_bf16(float c[4], const unsigned a[4],
                                         const unsigned b0, const unsigned b1) {
    asm("mma.sync.aligned.m16n8k16.row.col.f32.bf16.bf16.f32 "
        "{%0,%1,%2,%3}, {%4,%5,%6,%7}, {%8,%9}, {%0,%1,%2,%3};"
        : "+f"(c[0]), "+f"(c[1]), "+f"(c[2]), "+f"(c[3])
        : "r"(a[0]), "r"(a[1]), "r"(a[2]), "r"(a[3]), "r"(b0), "r"(b1));
}

// ---------------------------------------------------------------------------
// g1: h = ReLU(BN(x @ w1 + b1))   M=65536, N=64, K=256
// Block = 128 px, 256 threads. Warp: 2 m-tiles x 4 n-tiles.
// 16 chunks of 16k, double-buffered smem + register prefetch, STATIC smem.
// ---------------------------------------------------------------------------
#define XS_S 12     // 8 kp + 4 pad (A-frag banks 12*gid+tg all distinct)
#define W1_T 72     // 64 n + 8 pad (B-frag banks 8*tg+gid all distinct)
// smem layout (u32): xs_hi buf: cur*1536       [0,3072)
//                    xs_lo buf: 3072+cur*1536  [3072,6144)
//                    w1_hi buf: 6144+cur*576   [6144,7296)
//                    w1_lo buf: 7296+cur*576   [7296,8448)
#define G1_SM_U32 8448   // 33,792 B static

__global__ void __launch_bounds__(256, 3)
g1_kernel(const float* __restrict__ x,
          const float* __restrict__ w1,
          const float* __restrict__ b1,
          const float* __restrict__ gamma,
          const float* __restrict__ beta,
          const float* __restrict__ bn_mean,
          const float* __restrict__ bn_var)
{
    __shared__ unsigned sm[G1_SM_U32];

    const int t    = threadIdx.x;
    const int warp = t >> 5;
    const int lane = t & 31;
    const int gid  = lane >> 2;
    const int tg   = lane & 3;
    const int px0  = (warp & 3) * 32;
    const int nb   = (warp >> 2) * 32;
    const int rowbase = blockIdx.x * (128 * CC);

    // staging coordinates (fixed per thread)
    const int spx = t >> 2;        // x-stage px (0..63), second row +64
    const int skq = t & 3;         // x-stage float4 quad (covers kp 2skq,2skq+1)
    const bool wstage = (t < 128); // w1 staged by first 128 threads
    const int wkp = t >> 4;        // w1 k-pair within chunk (0..7)
    const int wnq = t & 15;        // w1 col quad (0..15)

    float c[2][4][4];
#pragma unroll
    for (int mt = 0; mt < 2; ++mt)
#pragma unroll
        for (int nt = 0; nt < 4; ++nt)
#pragma unroll
            for (int i = 0; i < 4; ++i) c[mt][nt][i] = 0.f;

    // --- prefetch chunk 0 ---
    float4 xr0, xr1, wra, wrb;
    {
        const float* xp = x + rowbase + spx * CC + skq * 4;
        xr0 = *(const float4*)xp;
        xr1 = *(const float4*)(xp + 64 * CC);
        if (wstage) {
            const float* wp = w1 + (2 * wkp) * CR + wnq * 4;
            wra = *(const float4*)wp;
            wrb = *(const float4*)(wp + CR);
        }
    }

#pragma unroll 1
    for (int ci = 0; ci < 16; ++ci) {
        const int cur = ci & 1;
        unsigned* xh = sm + cur * 1536;
        unsigned* xl = sm + 3072 + cur * 1536;
        unsigned* wh = sm + 6144 + cur * 576;
        unsigned* wl = sm + 7296 + cur * 576;

        // --- STS: split prefetched chunk into current buffer ---
        {
            unsigned h0, l0, h1, l1;
            int o = spx * XS_S + 2 * skq;
            pack_split(xr0.x, xr0.y, h0, l0);
            pack_split(xr0.z, xr0.w, h1, l1);
            xh[o] = h0; xh[o + 1] = h1; xl[o] = l0; xl[o + 1] = l1;
            o += 64 * XS_S;
            pack_split(xr1.x, xr1.y, h0, l0);
            pack_split(xr1.z, xr1.w, h1, l1);
            xh[o] = h0; xh[o + 1] = h1; xl[o] = l0; xl[o + 1] = l1;

            if (wstage) {
                uint4 hh, ll;
                pack_split(wra.x, wrb.x, hh.x, ll.x);
                pack_split(wra.y, wrb.y, hh.y, ll.y);
                pack_split(wra.z, wrb.z, hh.z, ll.z);
                pack_split(wra.w, wrb.w, hh.w, ll.w);
                *(uint4*)&wh[wkp * W1_T + wnq * 4] = hh;
                *(uint4*)&wl[wkp * W1_T + wnq * 4] = ll;
            }
        }
        __syncthreads();

        // --- prefetch next chunk (LDG latency overlapped by compute) ---
        if (ci < 15) {
            const int kc = (ci + 1) * 16;
            const float* xp = x + rowbase + spx * CC + kc + skq * 4;
            xr0 = *(const float4*)xp;
            xr1 = *(const float4*)(xp + 64 * CC);
            if (wstage) {
                const float* wp = w1 + (kc + 2 * wkp) * CR + wnq * 4;
                wra = *(const float4*)wp;
                wrb = *(const float4*)(wp + CR);
            }
        }

        // --- compute: one k16 step on current buffers ---
        {
            unsigned ah[2][4], al[2][4];
#pragma unroll
            for (int mt = 0; mt < 2; ++mt) {
                const int pr = px0 + mt * 16 + gid;
                ah[mt][0] = xh[pr * XS_S + tg];
                ah[mt][1] = xh[(pr + 8) * XS_S + tg];
                ah[mt][2] = xh[pr * XS_S + tg + 4];
                ah[mt][3] = xh[(pr + 8) * XS_S + tg + 4];
                al[mt][0] = xl[pr * XS_S + tg];
                al[mt][1] = xl[(pr + 8) * XS_S + tg];
                al[mt][2] = xl[pr * XS_S + tg + 4];
                al[mt][3] = xl[(pr + 8) * XS_S + tg + 4];
            }
#pragma unroll
            for (int nt = 0; nt < 4; ++nt) {
                const int col = nb + nt * 8 + gid;
                const unsigned bh0 = wh[tg * W1_T + col];
                const unsigned bh1 = wh[(tg + 4) * W1_T + col];
                const unsigned bl0 = wl[tg * W1_T + col];
                const unsigned bl1 = wl[(tg + 4) * W1_T + col];
#pragma unroll
                for (int mt = 0; mt < 2; ++mt) {
                    mma_bf16(c[mt][nt], ah[mt], bh0, bh1);
                    mma_bf16(c[mt][nt], ah[mt], bl0, bl1);
                    mma_bf16(c[mt][nt], al[mt], bh0, bh1);
                }
            }
        }
        // no trailing sync: STS(ci+2) into this buffer is ordered after
        // sync(ci+1), which follows every warp's compute(ci).
    }

    // epilogue: BN + ReLU, split to bf16, store packed hi/lo to g_h
#pragma unroll
    for (int nt = 0; nt < 4; ++nt) {
        const int d0 = nb + nt * 8 + 2 * tg;
        const int d1 = d0 + 1;
        const float s0  = gamma[d0] * rsqrtf(bn_var[d0] + BN_EPS);
        const float s1  = gamma[d1] * rsqrtf(bn_var[d1] + BN_EPS);
        const float sh0 = beta[d0] + (b1[d0] - bn_mean[d0]) * s0;
        const float sh1 = beta[d1] + (b1[d1] - bn_mean[d1]) * s1;
        const int kp = (nb >> 1) + nt * 4 + tg;
#pragma unroll
        for (int mt = 0; mt < 2; ++mt) {
            const int r0 = blockIdx.x * 128 + px0 + mt * 16 + gid;
            const int r1 = r0 + 8;
            const float v0e = fmaxf(c[mt][nt][0] * s0 + sh0, 0.f);
            const float v0o = fmaxf(c[mt][nt][1] * s1 + sh1, 0.f);
            const float v1e = fmaxf(c[mt][nt][2] * s0 + sh0, 0.f);
            const float v1o = fmaxf(c[mt][nt][3] * s1 + sh1, 0.f);
            unsigned h0, l0, h1, l1;
            pack_split(v0e, v0o, h0, l0);
            pack_split(v1e, v1o, h1, l1);
            g_h_hi[r0 * 32 + kp] = h0;
            g_h_lo[r0 * 32 + kp] = l0;
            g_h_hi[r1 * 32 + kp] = h1;
            g_h_lo[r1 * 32 + kp] = l1;
        }
    }
}

// ---------------------------------------------------------------------------
// g2: ker = h @ w2 + b2   M=65536, N=144, K=64  (round-5 known-good version)
// ---------------------------------------------------------------------------
#define HS_S 20
#define W2_T 168   // 144 + 24 pad (168%32==8)

__global__ void __launch_bounds__(256, 2)
g2_kernel(const float* __restrict__ w2,
          const float* __restrict__ b2,
          float* __restrict__ ker_out)
{
    __shared__ unsigned hs_hi[128 * HS_S];
    __shared__ unsigned hs_lo[128 * HS_S];
    __shared__ unsigned w2s_hi[16 * W2_T];
    __shared__ unsigned w2s_lo[16 * W2_T];

    const int t    = threadIdx.x;
    const int warp = t >> 5;
    const int lane = t & 31;
    const int gid  = lane >> 2;
    const int tg   = lane & 3;
    const int px0  = (warp & 3) * 32;
    const int nbase = (warp >> 2) * 72;

    float c[2][9][4];
#pragma unroll
    for (int mt = 0; mt < 2; ++mt)
#pragma unroll
        for (int nt = 0; nt < 9; ++nt)
#pragma unroll
            for (int i = 0; i < 4; ++i) c[mt][nt][i] = 0.f;

#pragma unroll 1
    for (int kc2 = 0; kc2 < 32; kc2 += 16) {
        // stage h (pre-split): pure copies
#pragma unroll
        for (int r = 0; r < 2; ++r) {
            const int i4 = t + 256 * r;
            const int px = i4 >> 2, kq = i4 & 3;
            const int gidx = (blockIdx.x * 128 + px) * 32 + kc2 + kq * 4;
            *(uint4*)&hs_hi[px * HS_S + kq * 4] = *(const uint4*)&g_h_hi[gidx];
            *(uint4*)&hs_lo[px * HS_S + kq * 4] = *(const uint4*)&g_h_lo[gidx];
        }
        // stage w2: 32 k x 144 n -> packed k-pairs, split
        for (int idx = t; idx < 576; idx += 256) {
            const int kp = idx & 15;
            const int nq = idx >> 4;
            const int grow = (kc2 + kp) * 2;
            const float4 va = *(const float4*)&w2[grow * EE + nq * 4];
            const float4 vb = *(const float4*)&w2[(grow + 1) * EE + nq * 4];
            uint4 hh, ll;
            pack_split(va.x, vb.x, hh.x, ll.x);
            pack_split(va.y, vb.y, hh.y, ll.y);
            pack_split(va.z, vb.z, hh.z, ll.z);
            pack_split(va.w, vb.w, hh.w, ll.w);
            *(uint4*)&w2s_hi[kp * W2_T + nq * 4] = hh;
            *(uint4*)&w2s_lo[kp * W2_T + nq * 4] = ll;
        }
        __syncthreads();

#pragma unroll
        for (int ks = 0; ks < 2; ++ks) {
            const int base = ks * 8;
#pragma unroll
            for (int mt = 0; mt < 2; ++mt) {
                const int pr = px0 + mt * 16 + gid;
                unsigned ah[4], al[4];
                ah[0] = hs_hi[pr * HS_S + base + tg];
                ah[1] = hs_hi[(pr + 8) * HS_S + base + tg];
                ah[2] = hs_hi[pr * HS_S + base + tg + 4];
                ah[3] = hs_hi[(pr + 8) * HS_S + base + tg + 4];
                al[0] = hs_lo[pr * HS_S + base + tg];
                al[1] = hs_lo[(pr + 8) * HS_S + base + tg];
                al[2] = hs_lo[pr * HS_S + base + tg + 4];
                al[3] = hs_lo[(pr + 8) * HS_S + base + tg + 4];
#pragma unroll
                for (int nt = 0; nt < 9; ++nt) {
                    const int col = nbase + nt * 8 + gid;
                    const unsigned bh0 = w2s_hi[(base + tg) * W2_T + col];
                    const unsigned bh1 = w2s_hi[(base + tg + 4) * W2_T + col];
                    const unsigned bl0 = w2s_lo[(base + tg) * W2_T + col];
                    const unsigned bl1 = w2s_lo[(base + tg + 4) * W2_T + col];
                    mma_bf16(c[mt][nt], ah, bh0, bh1);
                    mma_bf16(c[mt][nt], ah, bl0, bl1);
                    mma_bf16(c[mt][nt], al, bh0, bh1);
                }
            }
        }
        __syncthreads();
    }

    // epilogue: + b2 -> ker_out (fp32)
#pragma unroll
    for (int nt = 0; nt < 9; ++nt) {
        const int e0 = nbase + nt * 8 + 2 * tg;
        const float2 bb = *(const float2*)&b2[e0];
#pragma unroll
        for (int mt = 0; mt < 2; ++mt) {
            const int r0 = blockIdx.x * 128 + px0 + mt * 16 + gid;
            const int r1 = r0 + 8;
            float2 v0, v1;
            v0.x = c[mt][nt][0] + bb.x;
            v0.y = c[mt][nt][1] + bb.y;
            v1.x = c[mt][nt][2] + bb.x;
            v1.y = c[mt][nt][3] + bb.y;
            *(float2*)&ker_out[r0 * EE + e0] = v0;
            *(float2*)&ker_out[r1 * EE + e0] = v1;
        }
    }
}

// ---------------------------------------------------------------------------
// Kernel C: involution apply — 2 channels per thread (round-5 version)
// ---------------------------------------------------------------------------
__global__ void __launch_bounds__(128)
invo_apply(const float* __restrict__ x,
           const float* __restrict__ ker,
           float* __restrict__ out)
{
    __shared__ float ks[32 * EE];

    const int bid = blockIdx.x;
    const int wt  = bid & 3;
    const int h   = (bid >> 2) & 127;
    const int b   = bid >> 9;
    const int t   = threadIdx.x;
    const int g   = t & 15;
    const int w0  = wt * 32;

    const int kbase = ((b * HH + h) * WW + w0) * EE;
#pragma unroll
    for (int r = 0; r < 36; ++r) {
        const int idx = t + 128 * r;
        ks[idx] = ker[kbase + idx];
    }
    __syncthreads();

    const float* xm = x + ((b * HH + h) * WW) * CC + t;
    const float* xu = xm - WW * CC;
    const float* xd = xm + WW * CC;
    const bool up_ok = (h > 0);
    const bool dn_ok = (h < HH - 1);
    float* op = out + ((b * HH + h) * WW + w0) * CC + t;

    float uLa = 0.f, uMa = 0.f, mLa = 0.f, mMa = 0.f, dLa = 0.f, dMa = 0.f;
    float uLb = 0.f, uMb = 0.f, mLb = 0.f, mMb = 0.f, dLb = 0.f, dMb = 0.f;
    if (w0 > 0) {
        const int o = (w0 - 1) * CC;
        if (up_ok) { uLa = xu[o]; uLb = xu[o + 128]; }
        mLa = xm[o]; mLb = xm[o + 128];
        if (dn_ok) { dLa = xd[o]; dLb = xd[o + 128]; }
    }
    {
        const int o = w0 * CC;
        if (up_ok) { uMa = xu[o]; uMb = xu[o + 128]; }
        mMa = xm[o]; mMb = xm[o + 128];
        if (dn_ok) { dMa = xd[o]; dMb = xd[o + 128]; }
    }

#pragma unroll 4
    for (int i = 0; i < 32; ++i) {
        const int wr = w0 + i + 1;
        const bool rok = (wr < WW);
        float uRa = 0.f, mRa = 0.f, dRa = 0.f;
        float uRb = 0.f, mRb = 0.f, dRb = 0.f;
        if (rok) {
            const int o = wr * CC;
            if (up_ok) { uRa = xu[o]; uRb = xu[o + 128]; }
            mRa = xm[o]; mRb = xm[o + 128];
            if (dn_ok) { dRa = xd[o]; dRb = xd[o + 128]; }
        }
        const float* kk = &ks[i * EE + g];
        const float k0 = kk[0 * 16], k1 = kk[1 * 16], k2 = kk[2 * 16];
        const float k3 = kk[3 * 16], k4 = kk[4 * 16], k5 = kk[5 * 16];
        const float k6 = kk[6 * 16], k7 = kk[7 * 16], k8 = kk[8 * 16];

        float a = uLa * k0 + uMa * k1 + uRa * k2
                + mLa * k3 + mMa * k4 + mRa * k5
                + dLa * k6 + dMa * k7 + dRa * k8;
        float bv = uLb * k0 + uMb * k1 + uRb * k2
                 + mLb * k3 + mMb * k4 + mRb * k5
                 + dLb * k6 + dMb * k7 + dRb * k8;
        op[i * CC] = a;
        op[i * CC + 128] = bv;

        uLa = uMa; uMa = uRa; mLa = mMa; mMa = mRa; dLa = dMa; dMa = dRa;
        uLb = uMb; uMb = uRb; mLb = mMb; mMb = mRb; dLb = dMb; dMb = dRb;
    }
}

extern "C" void kernel_launch(void* const* d_in, const int* in_sizes, int n_in,
                              void* d_out, int out_size) {
    const float* x       = (const float*)d_in[0];
    const float* w1      = (const float*)d_in[1];
    const float* b1      = (const float*)d_in[2];
    const float* gamma   = (const float*)d_in[3];
    const float* beta    = (const float*)d_in[4];
    const float* bn_mean = (const float*)d_in[5];
    const float* bn_var  = (const float*)d_in[6];
    const float* w2      = (const float*)d_in[7];
    const float* b2      = (const float*)d_in[8];

    float* out     = (float*)d_out;
    float* ker_out = out + OUT1;

    // Pure kernel launches only — fully graph-capturable, no attribute calls.
    g1_kernel<<<NPX / 128, 256>>>(x, w1, b1, gamma, beta, bn_mean, bn_var);
    g2_kernel<<<NPX / 128, 256>>>(w2, b2, ker_out);
    invo_apply<<<BB * HH * 4, 128>>>(x, ker_out, out);
}

// round 8
// speedup vs baseline: 5.4637x; 1.1316x over previous
#include <cuda_runtime.h>

#define BB   4
#define HH   128
#define WW   128
#define CC   256
#define GG   16
#define CR   64
#define EE   144
#define BN_EPS 1e-3f

#define NPX  (BB*HH*WW)      // 65536 pixels
#define OUT1 (NPX*CC)        // 16,777,216

// ---------------------------------------------------------------------------
// helpers
// ---------------------------------------------------------------------------
__device__ __forceinline__ void pack_split(float fe, float fo,
                                           unsigned& hi, unsigned& lo) {
    unsigned h;
    asm("cvt.rn.bf16x2.f32 %0, %1, %2;" : "=r"(h) : "f"(fo), "f"(fe));
    const float he = __uint_as_float(h << 16);
    const float ho = __uint_as_float(h & 0xffff0000u);
    const float re = fe - he;
    const float ro = fo - ho;
    unsigned l;
    asm("cvt.rn.bf16x2.f32 %0, %1, %2;" : "=r"(l) : "f"(ro), "f"(re));
    hi = h; lo = l;
}

__device__ __forceinline__ void mma_bf16(float c[4], const unsigned a[4],
                                         const unsigned b0, const unsigned b1) {
    asm("mma.sync.aligned.m16n8k16.row.col.f32.bf16.bf16.f32 "
        "{%0,%1,%2,%3}, {%4,%5,%6,%7}, {%8,%9}, {%0,%1,%2,%3};"
        : "+f"(c[0]), "+f"(c[1]), "+f"(c[2]), "+f"(c[3])
        : "r"(a[0]), "r"(a[1]), "r"(a[2]), "r"(a[3]), "r"(b0), "r"(b1));
}

__device__ __forceinline__ unsigned smem_u32addr(const void* p) {
    return (unsigned)__cvta_generic_to_shared(p);
}
__device__ __forceinline__ void cp_async16(unsigned saddr, const void* g) {
    asm volatile("cp.async.cg.shared.global [%0], [%1], 16;"
                 :: "r"(saddr), "l"(g));
}

// ---------------------------------------------------------------------------
// Fused kernel: h = ReLU(BN(x@w1+b1)) in smem, then ker = h@w2 + b2.
// Block = 128 px (one image row), 256 threads, occ 3.
//
// Static smem layout (u32 units), total 10624 u32 = 42,496 B:
//   Phase A:  xs raw fp32, 2 bufs x 3072      [0, 6144)
//             w1 split,    2 bufs x 1152      [6144, 8448)   (hi 576 | lo 576)
//   Phase B:  h_hi 128x36                     [0, 4608)      (aliases phase A)
//             h_lo 128x36                     [4608, 9216)
//             w2 chunk hi 8x88 | lo 8x88      [9216, 10624)
// ---------------------------------------------------------------------------
#define XRAW_S 24    // fp32 stride/px: 16 k + 8 pad (LDS.64 conflict-free)
#define W1_T   72    // u32 stride/kp (8*tg+gid distinct banks)
#define HS_T   36    // u32 stride/px for h (4*gid+tg distinct banks)
#define W2_T   88    // u32 stride/kp for w2 chunk (24*tg+gid distinct banks)
#define SM_U32 10624

__global__ void __launch_bounds__(256, 3)
fused_kernel(const float* __restrict__ x,
             const float* __restrict__ w1,
             const float* __restrict__ b1,
             const float* __restrict__ gamma,
             const float* __restrict__ beta,
             const float* __restrict__ bn_mean,
             const float* __restrict__ bn_var,
             const float* __restrict__ w2,
             const float* __restrict__ b2,
             float* __restrict__ ker_out)
{
    __shared__ unsigned sm[SM_U32];
    float*    xs  = (float*)sm;        // phase A raw x (2 bufs)
    unsigned* w1b = sm + 6144;         // phase A w1 split (2 bufs)
    unsigned* hh  = sm;                // phase B h hi (alias)
    unsigned* hl  = sm + 4608;         // phase B h lo
    unsigned* w2h = sm + 9216;         // phase B w2 chunk hi
    unsigned* w2l = sm + 9920;         // phase B w2 chunk lo

    const int t    = threadIdx.x;
    const int warp = t >> 5;
    const int lane = t & 31;
    const int gid  = lane >> 2;
    const int tg   = lane & 3;
    const int pxw  = warp * 16;                 // warp owns px [pxw, pxw+16)
    const int rowbase = blockIdx.x * (128 * CC);

    // ---------------- Phase A: h = ReLU(BN(x @ w1 + b1)) ----------------
    // x: cp.async raw fp32 double buffer; w1: LDG prefetch + split STS.
    const int wkp = t >> 4;        // w1 k-pair in chunk (0..7), t<128
    const int wnq = t & 15;        // w1 col quad

    float4 wra, wrb;
    if (t < 128) {
        const float* wp = w1 + (2 * wkp) * CR + wnq * 4;
        wra = *(const float4*)wp;
        wrb = *(const float4*)(wp + CR);
    }
    // issue x chunk 0
    {
        const int s0 = t, s1 = t + 256;
        cp_async16(smem_u32addr(&xs[(s0 >> 2) * XRAW_S + (s0 & 3) * 4]),
                   &x[rowbase + (s0 >> 2) * CC + (s0 & 3) * 4]);
        cp_async16(smem_u32addr(&xs[(s1 >> 2) * XRAW_S + (s1 & 3) * 4]),
                   &x[rowbase + (s1 >> 2) * CC + (s1 & 3) * 4]);
        asm volatile("cp.async.commit_group;");
    }

    float c1[8][4];
#pragma unroll
    for (int nt = 0; nt < 8; ++nt)
#pragma unroll
        for (int i = 0; i < 4; ++i) c1[nt][i] = 0.f;

#pragma unroll 1
    for (int ci = 0; ci < 16; ++ci) {
        asm volatile("cp.async.wait_group 0;");
        __syncthreads();   // chunk ci visible block-wide; prev compute done

        // issue x chunk ci+1 into the other buffer
        if (ci < 15) {
            const int kc = (ci + 1) * 16;
            float* xb = xs + ((ci + 1) & 1) * 3072;
            const int s0 = t, s1 = t + 256;
            cp_async16(smem_u32addr(&xb[(s0 >> 2) * XRAW_S + (s0 & 3) * 4]),
                       &x[rowbase + (s0 >> 2) * CC + kc + (s0 & 3) * 4]);
            cp_async16(smem_u32addr(&xb[(s1 >> 2) * XRAW_S + (s1 & 3) * 4]),
                       &x[rowbase + (s1 >> 2) * CC + kc + (s1 & 3) * 4]);
            asm volatile("cp.async.commit_group;");
        }

        // STS w1 chunk ci (from prefetched regs)
        {
            unsigned* wh = w1b + (ci & 1) * 1152;
            unsigned* wl = wh + 576;
            if (t < 128) {
                uint4 hv, lv;
                pack_split(wra.x, wrb.x, hv.x, lv.x);
                pack_split(wra.y, wrb.y, hv.y, lv.y);
                pack_split(wra.z, wrb.z, hv.z, lv.z);
                pack_split(wra.w, wrb.w, hv.w, lv.w);
                *(uint4*)&wh[wkp * W1_T + wnq * 4] = hv;
                *(uint4*)&wl[wkp * W1_T + wnq * 4] = lv;
            }
        }
        // prefetch w1 chunk ci+1
        if (ci < 15 && t < 128) {
            const float* wp = w1 + ((ci + 1) * 16 + 2 * wkp) * CR + wnq * 4;
            wra = *(const float4*)wp;
            wrb = *(const float4*)(wp + CR);
        }
        __syncthreads();   // w1 STS visible

        // compute chunk ci: one k16 step
        {
            const float* xb = xs + (ci & 1) * 3072;
            const unsigned* wh = w1b + (ci & 1) * 1152;
            const unsigned* wl = wh + 576;

            unsigned ah[4], al[4];
            float2 f;
            f = *(const float2*)&xb[(pxw + gid) * XRAW_S + 2 * tg];
            pack_split(f.x, f.y, ah[0], al[0]);
            f = *(const float2*)&xb[(pxw + 8 + gid) * XRAW_S + 2 * tg];
            pack_split(f.x, f.y, ah[1], al[1]);
            f = *(const float2*)&xb[(pxw + gid) * XRAW_S + 2 * (tg + 4)];
            pack_split(f.x, f.y, ah[2], al[2]);
            f = *(const float2*)&xb[(pxw + 8 + gid) * XRAW_S + 2 * (tg + 4)];
            pack_split(f.x, f.y, ah[3], al[3]);

#pragma unroll
            for (int nt = 0; nt < 8; ++nt) {
                const int col = nt * 8 + gid;
                const unsigned bh0 = wh[tg * W1_T + col];
                const unsigned bh1 = wh[(tg + 4) * W1_T + col];
                const unsigned bl0 = wl[tg * W1_T + col];
                const unsigned bl1 = wl[(tg + 4) * W1_T + col];
                mma_bf16(c1[nt], ah, bh0, bh1);
                mma_bf16(c1[nt], ah, bl0, bl1);
                mma_bf16(c1[nt], al, bh0, bh1);
            }
        }
    }
    __syncthreads();   // all compute done before h overwrites xs/w1 region

    // epilogue A: BN + ReLU -> pre-split h in smem
#pragma unroll
    for (int nt = 0; nt < 8; ++nt) {
        const int d0 = nt * 8 + 2 * tg;
        const int d1 = d0 + 1;
        const float s0  = gamma[d0] * rsqrtf(bn_var[d0] + BN_EPS);
        const float s1  = gamma[d1] * rsqrtf(bn_var[d1] + BN_EPS);
        const float sh0 = beta[d0] + (b1[d0] - bn_mean[d0]) * s0;
        const float sh1 = beta[d1] + (b1[d1] - bn_mean[d1]) * s1;
        const int kp = nt * 4 + tg;          // k-pair = d0/2
        const int r0 = pxw + gid, r1 = r0 + 8;
        const float v0e = fmaxf(c1[nt][0] * s0 + sh0, 0.f);
        const float v0o = fmaxf(c1[nt][1] * s1 + sh1, 0.f);
        const float v1e = fmaxf(c1[nt][2] * s0 + sh0, 0.f);
        const float v1o = fmaxf(c1[nt][3] * s1 + sh1, 0.f);
        unsigned h0, l0, h1, l1;
        pack_split(v0e, v0o, h0, l0);
        pack_split(v1e, v1o, h1, l1);
        hh[r0 * HS_T + kp] = h0;  hl[r0 * HS_T + kp] = l0;
        hh[r1 * HS_T + kp] = h1;  hl[r1 * HS_T + kp] = l1;
    }
    __syncthreads();   // h visible to all warps

    // ---------------- Phase B: ker = h @ w2 + b2 ----------------
    // 2 e-passes of 72 cols x 4 k-chunks of 16. Warp: 16 px x 9 n-tiles.
    const int qkp = t / 18;              // t<144: w2-stage k-pair (0..7)
    const int qnq = t - qkp * 18;        //        col quad (0..17)

    float4 va, vb;
    if (t < 144) {
        const int row = 2 * qkp;         // pass 0, chunk 0
        va = *(const float4*)&w2[row * EE + qnq * 4];
        vb = *(const float4*)&w2[(row + 1) * EE + qnq * 4];
    }

#pragma unroll 1
    for (int pass = 0; pass < 2; ++pass) {
        float c2[9][4];
#pragma unroll
        for (int nt = 0; nt < 9; ++nt)
#pragma unroll
            for (int i = 0; i < 4; ++i) c2[nt][i] = 0.f;

#pragma unroll 1
        for (int ck = 0; ck < 4; ++ck) {
            // STS current w2 chunk (from prefetched regs)
            if (t < 144) {
                uint4 hv, lv;
                pack_split(va.x, vb.x, hv.x, lv.x);
                pack_split(va.y, vb.y, hv.y, lv.y);
                pack_split(va.z, vb.z, hv.z, lv.z);
                pack_split(va.w, vb.w, hv.w, lv.w);
                *(uint4*)&w2h[qkp * W2_T + qnq * 4] = hv;
                *(uint4*)&w2l[qkp * W2_T + qnq * 4] = lv;
            }
            __syncthreads();

            // prefetch next w2 chunk
            const int it = pass * 4 + ck;
            if (it < 7 && t < 144) {
                const int np = (it + 1) >> 2, nc = (it + 1) & 3;
                const int row = (nc * 8 + qkp) * 2;
                va = *(const float4*)&w2[row * EE + np * 72 + qnq * 4];
                vb = *(const float4*)&w2[(row + 1) * EE + np * 72 + qnq * 4];
            }

            // compute: one k16 step
            {
                const int base = ck * 8;
                unsigned ah[4], al[4];
                ah[0] = hh[(pxw + gid) * HS_T + base + tg];
                ah[1] = hh[(pxw + 8 + gid) * HS_T + base + tg];
                ah[2] = hh[(pxw + gid) * HS_T + base + tg + 4];
                ah[3] = hh[(pxw + 8 + gid) * HS_T + base + tg + 4];
                al[0] = hl[(pxw + gid) * HS_T + base + tg];
                al[1] = hl[(pxw + 8 + gid) * HS_T + base + tg];
                al[2] = hl[(pxw + gid) * HS_T + base + tg + 4];
                al[3] = hl[(pxw + 8 + gid) * HS_T + base + tg + 4];
#pragma unroll
                for (int nt = 0; nt < 9; ++nt) {
                    const int col = nt * 8 + gid;
                    const unsigned bh0 = w2h[tg * W2_T + col];
                    const unsigned bh1 = w2h[(tg + 4) * W2_T + col];
                    const unsigned bl0 = w2l[tg * W2_T + col];
                    const unsigned bl1 = w2l[(tg + 4) * W2_T + col];
                    mma_bf16(c2[nt], ah, bh0, bh1);
                    mma_bf16(c2[nt], ah, bl0, bl1);
                    mma_bf16(c2[nt], al, bh0, bh1);
                }
            }
            __syncthreads();   // before w2 buffer reuse
        }

        // pass epilogue: + b2 -> ker_out
        const int r0g = blockIdx.x * 128 + pxw + gid;
        const int r1g = r0g + 8;
#pragma unroll
        for (int nt = 0; nt < 9; ++nt) {
            const int e0 = pass * 72 + nt * 8 + 2 * tg;
            const float2 bb = *(const float2*)&b2[e0];
            float2 v0, v1;
            v0.x = c2[nt][0] + bb.x;  v0.y = c2[nt][1] + bb.y;
            v1.x = c2[nt][2] + bb.x;  v1.y = c2[nt][3] + bb.y;
            *(float2*)&ker_out[r0g * EE + e0] = v0;
            *(float2*)&ker_out[r1g * EE + e0] = v1;
        }
    }
}

// ---------------------------------------------------------------------------
// Involution apply — 2 channels per thread (unchanged; ~36us, DRAM-bound)
// ---------------------------------------------------------------------------
__global__ void __launch_bounds__(128)
invo_apply(const float* __restrict__ x,
           const float* __restrict__ ker,
           float* __restrict__ out)
{
    __shared__ float ks[32 * EE];

    const int bid = blockIdx.x;
    const int wt  = bid & 3;
    const int h   = (bid >> 2) & 127;
    const int b   = bid >> 9;
    const int t   = threadIdx.x;
    const int g   = t & 15;
    const int w0  = wt * 32;

    const int kbase = ((b * HH + h) * WW + w0) * EE;
#pragma unroll
    for (int r = 0; r < 36; ++r) {
        const int idx = t + 128 * r;
        ks[idx] = ker[kbase + idx];
    }
    __syncthreads();

    const float* xm = x + ((b * HH + h) * WW) * CC + t;
    const float* xu = xm - WW * CC;
    const float* xd = xm + WW * CC;
    const bool up_ok = (h > 0);
    const bool dn_ok = (h < HH - 1);
    float* op = out + ((b * HH + h) * WW + w0) * CC + t;

    float uLa = 0.f, uMa = 0.f, mLa = 0.f, mMa = 0.f, dLa = 0.f, dMa = 0.f;
    float uLb = 0.f, uMb = 0.f, mLb = 0.f, mMb = 0.f, dLb = 0.f, dMb = 0.f;
    if (w0 > 0) {
        const int o = (w0 - 1) * CC;
        if (up_ok) { uLa = xu[o]; uLb = xu[o + 128]; }
        mLa = xm[o]; mLb = xm[o + 128];
        if (dn_ok) { dLa = xd[o]; dLb = xd[o + 128]; }
    }
    {
        const int o = w0 * CC;
        if (up_ok) { uMa = xu[o]; uMb = xu[o + 128]; }
        mMa = xm[o]; mMb = xm[o + 128];
        if (dn_ok) { dMa = xd[o]; dMb = xd[o + 128]; }
    }

#pragma unroll 4
    for (int i = 0; i < 32; ++i) {
        const int wr = w0 + i + 1;
        const bool rok = (wr < WW);
        float uRa = 0.f, mRa = 0.f, dRa = 0.f;
        float uRb = 0.f, mRb = 0.f, dRb = 0.f;
        if (rok) {
            const int o = wr * CC;
            if (up_ok) { uRa = xu[o]; uRb = xu[o + 128]; }
            mRa = xm[o]; mRb = xm[o + 128];
            if (dn_ok) { dRa = xd[o]; dRb = xd[o + 128]; }
        }
        const float* kk = &ks[i * EE + g];
        const float k0 = kk[0 * 16], k1 = kk[1 * 16], k2 = kk[2 * 16];
        const float k3 = kk[3 * 16], k4 = kk[4 * 16], k5 = kk[5 * 16];
        const float k6 = kk[6 * 16], k7 = kk[7 * 16], k8 = kk[8 * 16];

        float a = uLa * k0 + uMa * k1 + uRa * k2
                + mLa * k3 + mMa * k4 + mRa * k5
                + dLa * k6 + dMa * k7 + dRa * k8;
        float bv = uLb * k0 + uMb * k1 + uRb * k2
                 + mLb * k3 + mMb * k4 + mRb * k5
                 + dLb * k6 + dMb * k7 + dRb * k8;
        op[i * CC] = a;
        op[i * CC + 128] = bv;

        uLa = uMa; uMa = uRa; mLa = mMa; mMa = mRa; dLa = dMa; dMa = dRa;
        uLb = uMb; uMb = uRb; mLb = mMb; mMb = mRb; dLb = dMb; dMb = dRb;
    }
}

extern "C" void kernel_launch(void* const* d_in, const int* in_sizes, int n_in,
                              void* d_out, int out_size) {
    const float* x       = (const float*)d_in[0];
    const float* w1      = (const float*)d_in[1];
    const float* b1      = (const float*)d_in[2];
    const float* gamma   = (const float*)d_in[3];
    const float* beta    = (const float*)d_in[4];
    const float* bn_mean = (const float*)d_in[5];
    const float* bn_var  = (const float*)d_in[6];
    const float* w2      = (const float*)d_in[7];
    const float* b2      = (const float*)d_in[8];

    float* out     = (float*)d_out;
    float* ker_out = out + OUT1;

    fused_kernel<<<NPX / 128, 256>>>(x, w1, b1, gamma, beta, bn_mean, bn_var,
                                     w2, b2, ker_out);
    invo_apply<<<BB * HH * 4, 128>>>(x, ker_out, out);
}